// round 12
// baseline (speedup 1.0000x reference)
#include <cuda_runtime.h>
#include <cuda_bf16.h>
#include <cstdint>

// Problem constants (fixed by the dataset)
#define NN   50000
#define EE   600000
#define FD   128
#define EDIM 16
#define HH   4
#define DD   32
#define HIDD 128
#define CC   10

#define NCHUNK 196   // ceil(NN/256)

// ---------------------------------------------------------------------------
// Scratch (device globals; allocation-free per harness rules)
// ---------------------------------------------------------------------------
__device__ __align__(16) float d_qkvs[(size_t)NN * 512];   // q|k|v|skip packed per node
__device__ __align__(16) float d_h[(size_t)NN * 128];      // layer-0 output
// B in bf16 hi/lo, FRAGMENT-ordered, per layer
__device__ __align__(16) uint32_t d_WfH[2][8 * 16 * 32 * 8];
__device__ __align__(16) uint32_t d_WfL[2][8 * 16 * 32 * 8];
__device__ __align__(16) float d_bp[2][512];

// CSR-by-dst (built once per launch, shared by both layers)
__device__ int d_deg[NN];
__device__ int d_start[NN];
__device__ int d_cursor[NN];
__device__ int2 d_edge[EE];  // (edge id, src node) permuted by dst
__device__ int d_csums[256];
__device__ int d_coffs[256];

// ---------------------------------------------------------------------------
// Helpers
// ---------------------------------------------------------------------------
__device__ __forceinline__ int warp_incl_scan(int v, int lane) {
#pragma unroll
    for (int o = 1; o < 32; o <<= 1) {
        int n = __shfl_up_sync(0xffffffffu, v, o);
        if (lane >= o) v += n;
    }
    return v;
}

__device__ __forceinline__ void split_bf16x2(float f0, float f1,
                                             uint32_t& hi, uint32_t& lo) {
    __nv_bfloat162 hp = __float22bfloat162_rn(make_float2(f0, f1));
    hi = *reinterpret_cast<uint32_t*>(&hp);
    float r0 = f0 - __low2float(hp);
    float r1 = f1 - __high2float(hp);
    __nv_bfloat162 lp = __float22bfloat162_rn(make_float2(r0, r1));
    lo = *reinterpret_cast<uint32_t*>(&lp);
}

__device__ __forceinline__ uint32_t smem_u32(const void* p) {
    return (uint32_t)__cvta_generic_to_shared(p);
}

// ---------------------------------------------------------------------------
// CSR build
// ---------------------------------------------------------------------------
__global__ void zero_deg() {
    int i = blockIdx.x * blockDim.x + threadIdx.x;
    if (i < NN) d_deg[i] = 0;
}

__global__ void hist_kernel(const int* __restrict__ dst) {
    int e = blockIdx.x * blockDim.x + threadIdx.x;
    if (e < EE) atomicAdd(&d_deg[dst[e]], 1);
}

__global__ void chunk_sums() {
    int tid = threadIdx.x, b = blockIdx.x, i = b * 256 + tid;
    int v = (i < NN) ? d_deg[i] : 0;
#pragma unroll
    for (int o = 16; o > 0; o >>= 1) v += __shfl_xor_sync(0xffffffffu, v, o);
    __shared__ int ws[8];
    if ((tid & 31) == 0) ws[tid >> 5] = v;
    __syncthreads();
    if (tid == 0) {
        int s = 0;
#pragma unroll
        for (int k = 0; k < 8; k++) s += ws[k];
        d_csums[b] = s;
    }
}

__global__ void chunk_offsets() {   // single block, 256 threads
    int tid = threadIdx.x;
    int lane = tid & 31, w = tid >> 5;
    __shared__ int ws[8];
    int v = (tid < NCHUNK) ? d_csums[tid] : 0;
    int incl = warp_incl_scan(v, lane);
    if (lane == 31) ws[w] = incl;
    __syncthreads();
    if (w == 0) {
        int t = (lane < 8) ? ws[lane] : 0;
        t = warp_incl_scan(t, lane);
        if (lane < 8) ws[lane] = t;
    }
    __syncthreads();
    int excl = incl - v + (w > 0 ? ws[w - 1] : 0);
    d_coffs[tid] = excl;
}

__global__ void scan_chunks() {
    int tid = threadIdx.x, b = blockIdx.x, i = b * 256 + tid;
    int lane = tid & 31, w = tid >> 5;
    __shared__ int ws[8];
    int v = (i < NN) ? d_deg[i] : 0;
    int incl = warp_incl_scan(v, lane);
    if (lane == 31) ws[w] = incl;
    __syncthreads();
    if (w == 0) {
        int t = (lane < 8) ? ws[lane] : 0;
        t = warp_incl_scan(t, lane);
        if (lane < 8) ws[lane] = t;
    }
    __syncthreads();
    int excl = incl - v + (w > 0 ? ws[w - 1] : 0) + d_coffs[b];
    if (i < NN) { d_start[i] = excl; d_cursor[i] = excl; }
}

__global__ void scatter_perm(const int* __restrict__ dst, const int* __restrict__ src) {
    int e = blockIdx.x * blockDim.x + threadIdx.x;
    if (e < EE) {
        int pos = atomicAdd(&d_cursor[dst[e]], 1);
        d_edge[pos] = make_int2(e, src[e]);
    }
}

// ---------------------------------------------------------------------------
// Pack weights (per layer slot): bf16 hi/lo split, FRAGMENT order
// ---------------------------------------------------------------------------
__global__ void pack_kernel(const float* __restrict__ Wq, const float* __restrict__ Wk,
                            const float* __restrict__ Wv, const float* __restrict__ Ws,
                            const float* __restrict__ bq, const float* __restrict__ bk,
                            const float* __restrict__ bv, const float* __restrict__ bs,
                            int slot) {
    int idx = blockIdx.x * blockDim.x + threadIdx.x;
    if (idx < 64 * 512) {
        int kp = idx >> 9, col = idx & 511;
        int sel = col >> 7, jc = col & 127;
        const float* W = sel == 0 ? Wq : sel == 1 ? Wk : sel == 2 ? Wv : Ws;
        float f0 = W[(2 * kp) * 128 + jc];
        float f1 = W[(2 * kp + 1) * 128 + jc];
        uint32_t hi, lo;
        split_bf16x2(f0, f1, hi, lo);
        int ch = kp >> 3, kpl = kp & 7;
        int kh = kpl >> 2, tg = kpl & 3;
        int seg = col >> 5, g = col & 7, nt = (col >> 3) & 3;
        int off = ((ch * 16 + seg) * 32 + g * 4 + tg) * 8 + kh * 4 + nt;
        d_WfH[slot][off] = hi;
        d_WfL[slot][off] = lo;
    }
    if (idx < 512) {
        int sel = idx >> 7, jc = idx & 127;
        const float* b = sel == 0 ? bq : sel == 1 ? bk : sel == 2 ? bv : bs;
        d_bp[slot][idx] = b[jc];
    }
}

// ---------------------------------------------------------------------------
// bf16x3 tensor-core GEMM (R10 form, layer-indexed weights)
// ---------------------------------------------------------------------------
#define KC 16

__global__ void __launch_bounds__(256, 2) sgemm_bf16x3(const float* __restrict__ x,
                                                       int layer, int M) {
    const float* A = (layer == 0) ? x : (const float*)d_h;

    __shared__ __align__(16) uint32_t AsH[2][128][8];
    __shared__ __align__(16) uint32_t AsL[2][128][8];
    __shared__ __align__(16) uint32_t BfH[2][4][32][12];
    __shared__ __align__(16) uint32_t BfL[2][4][32][12];

    int tid = threadIdx.x;
    int bx = blockIdx.x;
    int by = blockIdx.y;
    int warp = tid >> 5, lane = tid & 31;
    int wm = warp >> 2, wn = warp & 3;
    int mbase = wm * 64, nbase = wn * 32;
    int rowBase = by * 128;
    int g = lane >> 2;
    int tg = lane & 3;

    int aR0 = tid >> 2,          aC0 = tid & 3;
    int aR1 = (tid + 256) >> 2,  aC1 = (tid + 256) & 3;
    int aI0a = (aC0 & 1) * 4 + (aC0 >> 1), aI0b = aI0a + 2;
    int aI1a = (aC1 & 1) * 4 + (aC1 >> 1), aI1b = aI1a + 2;

    float c[4][4][4];
#pragma unroll
    for (int i = 0; i < 4; i++)
#pragma unroll
        for (int j = 0; j < 4; j++)
#pragma unroll
            for (int r = 0; r < 4; r++) c[i][j][r] = 0.0f;

    float4 aReg0, aReg1;
    int grA0 = rowBase + aR0, grA1 = rowBase + aR1;
    bool a0OK = (grA0 < M), a1OK = (grA1 < M);

    int wnT = tid >> 6, laneT = (tid >> 1) & 31, halfT = tid & 1;
    uint32_t dBH0 = smem_u32(&BfH[0][0][0][0]) + ((wnT * 32 + laneT) * 12 + halfT * 4) * 4;
    uint32_t dBL0 = smem_u32(&BfL[0][0][0][0]) + ((wnT * 32 + laneT) * 12 + halfT * 4) * 4;
    const uint32_t* gBH = d_WfH[layer] + (size_t)bx * 4 * 256 + tid * 4;
    const uint32_t* gBL = d_WfL[layer] + (size_t)bx * 4 * 256 + tid * 4;
    const uint32_t stageBytes = 4 * 32 * 12 * 4;

    auto stageB = [&](int ch, int st) {
        uint32_t dH = dBH0 + st * stageBytes;
        uint32_t dL = dBL0 + st * stageBytes;
        const uint32_t* sH = gBH + ch * 4096;
        const uint32_t* sL = gBL + ch * 4096;
        asm volatile("cp.async.ca.shared.global [%0], [%1], 16;" :: "r"(dH), "l"(sH));
        asm volatile("cp.async.ca.shared.global [%0], [%1], 16;" :: "r"(dL), "l"(sL));
        asm volatile("cp.async.commit_group;");
    };

    auto loadA = [&](int ch) {
        int k0 = ch * KC;
        aReg0 = a0OK ? *(const float4*)(A + (size_t)grA0 * 128 + k0 + aC0 * 4)
                     : make_float4(0.f, 0.f, 0.f, 0.f);
        aReg1 = a1OK ? *(const float4*)(A + (size_t)grA1 * 128 + k0 + aC1 * 4)
                     : make_float4(0.f, 0.f, 0.f, 0.f);
    };

    auto storeA = [&](int st) {
        uint32_t h0, l0, h1, l1;
        split_bf16x2(aReg0.x, aReg0.y, h0, l0);
        split_bf16x2(aReg0.z, aReg0.w, h1, l1);
        AsH[st][aR0][aI0a] = h0;  AsH[st][aR0][aI0b] = h1;
        AsL[st][aR0][aI0a] = l0;  AsL[st][aR0][aI0b] = l1;
        split_bf16x2(aReg1.x, aReg1.y, h0, l0);
        split_bf16x2(aReg1.z, aReg1.w, h1, l1);
        AsH[st][aR1][aI1a] = h0;  AsH[st][aR1][aI1b] = h1;
        AsL[st][aR1][aI1a] = l0;  AsL[st][aR1][aI1b] = l1;
    };

    auto computeChunk = [&](int st) {
        const uint32_t* pH = &BfH[st][wn][lane][0];
        const uint32_t* pL = &BfL[st][wn][lane][0];
        uint4 bh0 = *(const uint4*)pH;
        uint4 bh1 = *(const uint4*)(pH + 4);
        uint4 bl0 = *(const uint4*)pL;
        uint4 bl1 = *(const uint4*)(pL + 4);
        uint32_t bh[4][2] = {{bh0.x, bh1.x}, {bh0.y, bh1.y}, {bh0.z, bh1.z}, {bh0.w, bh1.w}};
        uint32_t bl[4][2] = {{bl0.x, bl1.x}, {bl0.y, bl1.y}, {bl0.z, bl1.z}, {bl0.w, bl1.w}};
#pragma unroll
        for (int mt = 0; mt < 4; mt++) {
            int r = mbase + mt * 16 + g;
            uint2 ah0 = *(const uint2*)&AsH[st][r][2 * tg];
            uint2 ah1 = *(const uint2*)&AsH[st][r + 8][2 * tg];
            uint2 al0 = *(const uint2*)&AsL[st][r][2 * tg];
            uint2 al1 = *(const uint2*)&AsL[st][r + 8][2 * tg];
#pragma unroll
            for (int nt = 0; nt < 4; nt++) {
                float* cc = c[mt][nt];
                asm volatile(
                    "mma.sync.aligned.m16n8k16.row.col.f32.bf16.bf16.f32 "
                    "{%0,%1,%2,%3},{%4,%5,%6,%7},{%8,%9},{%0,%1,%2,%3};"
                    : "+f"(cc[0]), "+f"(cc[1]), "+f"(cc[2]), "+f"(cc[3])
                    : "r"(ah0.x), "r"(ah1.x), "r"(ah0.y), "r"(ah1.y),
                      "r"(bh[nt][0]), "r"(bh[nt][1]));
                asm volatile(
                    "mma.sync.aligned.m16n8k16.row.col.f32.bf16.bf16.f32 "
                    "{%0,%1,%2,%3},{%4,%5,%6,%7},{%8,%9},{%0,%1,%2,%3};"
                    : "+f"(cc[0]), "+f"(cc[1]), "+f"(cc[2]), "+f"(cc[3])
                    : "r"(ah0.x), "r"(ah1.x), "r"(ah0.y), "r"(ah1.y),
                      "r"(bl[nt][0]), "r"(bl[nt][1]));
                asm volatile(
                    "mma.sync.aligned.m16n8k16.row.col.f32.bf16.bf16.f32 "
                    "{%0,%1,%2,%3},{%4,%5,%6,%7},{%8,%9},{%0,%1,%2,%3};"
                    : "+f"(cc[0]), "+f"(cc[1]), "+f"(cc[2]), "+f"(cc[3])
                    : "r"(al0.x), "r"(al1.x), "r"(al0.y), "r"(al1.y),
                      "r"(bh[nt][0]), "r"(bh[nt][1]));
            }
        }
    };

    stageB(0, 0);
    loadA(0);
    storeA(0);
    asm volatile("cp.async.wait_group 0;" ::: "memory");
    __syncthreads();
#pragma unroll
    for (int ch = 0; ch < 8; ch++) {
        int cur = ch & 1;
        if (ch < 7) {
            loadA(ch + 1);
            stageB(ch + 1, cur ^ 1);
        }
        computeChunk(cur);
        if (ch < 7) {
            storeA(cur ^ 1);
            asm volatile("cp.async.wait_group 0;" ::: "memory");
            __syncthreads();
        }
    }

#pragma unroll
    for (int mt = 0; mt < 4; mt++) {
        int r0 = rowBase + mbase + mt * 16 + g;
        int r1 = r0 + 8;
#pragma unroll
        for (int nt = 0; nt < 4; nt++) {
            int col = bx * 128 + nbase + nt * 8 + 2 * tg;
            float2 b2 = *(const float2*)(d_bp[layer] + col);
            if (r0 < M) {
                float2 o = make_float2(c[mt][nt][0] + b2.x, c[mt][nt][1] + b2.y);
                *(float2*)(d_qkvs + (size_t)r0 * 512 + col) = o;
            }
            if (r1 < M) {
                float2 o = make_float2(c[mt][nt][2] + b2.x, c[mt][nt][3] + b2.y);
                *(float2*)(d_qkvs + (size_t)r1 * 512 + col) = o;
            }
        }
    }
}

// ---------------------------------------------------------------------------
// Node-centric attention, with optional fused output head (layer 1).
// doOut==0: write h to d_h.  doOut==1: logits+log_softmax straight to out.
// ---------------------------------------------------------------------------
__global__ void __launch_bounds__(128) attn_node(const float* __restrict__ eattr,
                                                 const float* __restrict__ We,
                                                 const float* __restrict__ Wout,
                                                 const float* __restrict__ bout,
                                                 float* __restrict__ out,
                                                 int doOut) {
    const unsigned FULL = 0xffffffffu;
    __shared__ float sW[128 * 10];
    __shared__ float sb[10];
    if (doOut) {
        for (int i = threadIdx.x; i < 128 * 10; i += 128) sW[i] = Wout[i];
        if (threadIdx.x < 10) sb[threadIdx.x] = bout[threadIdx.x];
        __syncthreads();
    }

    int warp = (blockIdx.x * 128 + threadIdx.x) >> 5;
    int lane = threadIdx.x & 31;
    if (warp >= NN) return;
    int n = warp;
    int p = lane & 7;
    int gb = lane & 24;

    float4 wreg[16];
#pragma unroll
    for (int k = 0; k < 16; k++)
        wreg[k] = __ldg((const float4*)(We + k * 128) + lane);

    float4 q4 = *(const float4*)(d_qkvs + (size_t)n * 512 + lane * 4);

    float pk[16];
#pragma unroll
    for (int k = 0; k < 16; k++)
        pk[k] = q4.x * wreg[k].x + q4.y * wreg[k].y +
                q4.z * wreg[k].z + q4.w * wreg[k].w;
    float u[8];
#pragma unroll
    for (int i = 0; i < 8; i++) {
        float keep  = (lane & 4) ? pk[i + 8] : pk[i];
        float other = (lane & 4) ? pk[i] : pk[i + 8];
        u[i] = keep + __shfl_xor_sync(FULL, other, 4);
    }
    float w4[4];
#pragma unroll
    for (int i = 0; i < 4; i++) {
        float keep  = (lane & 2) ? u[i + 4] : u[i];
        float other = (lane & 2) ? u[i] : u[i + 4];
        w4[i] = keep + __shfl_xor_sync(FULL, other, 2);
    }
    float z0, z1;
    {
        float k0 = (lane & 1) ? w4[2] : w4[0];
        float o0 = (lane & 1) ? w4[0] : w4[2];
        z0 = k0 + __shfl_xor_sync(FULL, o0, 1);
        float k1 = (lane & 1) ? w4[3] : w4[1];
        float o1 = (lane & 1) ? w4[1] : w4[3];
        z1 = k1 + __shfl_xor_sync(FULL, o1, 1);
    }

    float4 acc = make_float4(0.f, 0.f, 0.f, 0.f);
    float s0a = 0.0f, s1a = 0.0f;
    float dsum = 0.0f;

    int start = d_start[n];
    int deg = d_deg[n];
    const float SC = 0.17677669529663687f;

    int j = 0;
    for (; j + 3 < deg; j += 4) {
        int2 ed0 = __ldg(&d_edge[start + j]);
        int2 ed1 = __ldg(&d_edge[start + j + 1]);
        int2 ed2 = __ldg(&d_edge[start + j + 2]);
        int2 ed3 = __ldg(&d_edge[start + j + 3]);

        float2 ep0 = *(const float2*)(eattr + (size_t)ed0.x * 16 + 2 * p);
        float2 ep1 = *(const float2*)(eattr + (size_t)ed1.x * 16 + 2 * p);
        float2 ep2 = *(const float2*)(eattr + (size_t)ed2.x * 16 + 2 * p);
        float2 ep3 = *(const float2*)(eattr + (size_t)ed3.x * 16 + 2 * p);

        const float* b0 = d_qkvs + (size_t)ed0.y * 512;
        const float* b1 = d_qkvs + (size_t)ed1.y * 512;
        const float* b2 = d_qkvs + (size_t)ed2.y * 512;
        const float* b3 = d_qkvs + (size_t)ed3.y * 512;
        float4 k40 = *(const float4*)(b0 + 128 + lane * 4);
        float4 k41 = *(const float4*)(b1 + 128 + lane * 4);
        float4 k42 = *(const float4*)(b2 + 128 + lane * 4);
        float4 k43 = *(const float4*)(b3 + 128 + lane * 4);
        float4 v40 = *(const float4*)(b0 + 256 + lane * 4);
        float4 v41 = *(const float4*)(b1 + 256 + lane * 4);
        float4 v42 = *(const float4*)(b2 + 256 + lane * 4);
        float4 v43 = *(const float4*)(b3 + 256 + lane * 4);

        float t0 = q4.x * k40.x + q4.y * k40.y + q4.z * k40.z + q4.w * k40.w +
                   ep0.x * z0 + ep0.y * z1;
        float t1 = q4.x * k41.x + q4.y * k41.y + q4.z * k41.z + q4.w * k41.w +
                   ep1.x * z0 + ep1.y * z1;
        float t2 = q4.x * k42.x + q4.y * k42.y + q4.z * k42.z + q4.w * k42.w +
                   ep2.x * z0 + ep2.y * z1;
        float t3 = q4.x * k43.x + q4.y * k43.y + q4.z * k43.z + q4.w * k43.w +
                   ep3.x * z0 + ep3.y * z1;
        t0 += __shfl_xor_sync(FULL, t0, 1);
        t1 += __shfl_xor_sync(FULL, t1, 1);
        t2 += __shfl_xor_sync(FULL, t2, 1);
        t3 += __shfl_xor_sync(FULL, t3, 1);
        t0 += __shfl_xor_sync(FULL, t0, 2);
        t1 += __shfl_xor_sync(FULL, t1, 2);
        t2 += __shfl_xor_sync(FULL, t2, 2);
        t3 += __shfl_xor_sync(FULL, t3, 2);
        t0 += __shfl_xor_sync(FULL, t0, 4);
        t1 += __shfl_xor_sync(FULL, t1, 4);
        t2 += __shfl_xor_sync(FULL, t2, 4);
        t3 += __shfl_xor_sync(FULL, t3, 4);

        float ex0 = __expf(t0 * SC);
        float ex1 = __expf(t1 * SC);
        float ex2 = __expf(t2 * SC);
        float ex3 = __expf(t3 * SC);
        dsum += (ex0 + ex1) + (ex2 + ex3);
        acc.x = fmaf(v40.x, ex0, acc.x);  acc.x = fmaf(v41.x, ex1, acc.x);
        acc.x = fmaf(v42.x, ex2, acc.x);  acc.x = fmaf(v43.x, ex3, acc.x);
        acc.y = fmaf(v40.y, ex0, acc.y);  acc.y = fmaf(v41.y, ex1, acc.y);
        acc.y = fmaf(v42.y, ex2, acc.y);  acc.y = fmaf(v43.y, ex3, acc.y);
        acc.z = fmaf(v40.z, ex0, acc.z);  acc.z = fmaf(v41.z, ex1, acc.z);
        acc.z = fmaf(v42.z, ex2, acc.z);  acc.z = fmaf(v43.z, ex3, acc.z);
        acc.w = fmaf(v40.w, ex0, acc.w);  acc.w = fmaf(v41.w, ex1, acc.w);
        acc.w = fmaf(v42.w, ex2, acc.w);  acc.w = fmaf(v43.w, ex3, acc.w);
        s0a = fmaf(ep0.x, ex0, s0a);      s0a = fmaf(ep1.x, ex1, s0a);
        s0a = fmaf(ep2.x, ex2, s0a);      s0a = fmaf(ep3.x, ex3, s0a);
        s1a = fmaf(ep0.y, ex0, s1a);      s1a = fmaf(ep1.y, ex1, s1a);
        s1a = fmaf(ep2.y, ex2, s1a);      s1a = fmaf(ep3.y, ex3, s1a);
    }

    for (; j < deg; j++) {
        int2 ed = __ldg(&d_edge[start + j]);
        float2 ep = *(const float2*)(eattr + (size_t)ed.x * 16 + 2 * p);
        const float* base = d_qkvs + (size_t)ed.y * 512;
        float4 k4 = *(const float4*)(base + 128 + lane * 4);
        float4 v4 = *(const float4*)(base + 256 + lane * 4);
        float t = q4.x * k4.x + q4.y * k4.y + q4.z * k4.z + q4.w * k4.w +
                  ep.x * z0 + ep.y * z1;
        t += __shfl_xor_sync(FULL, t, 1);
        t += __shfl_xor_sync(FULL, t, 2);
        t += __shfl_xor_sync(FULL, t, 4);
        float ex = __expf(t * SC);
        dsum += ex;
        acc.x = fmaf(v4.x, ex, acc.x);
        acc.y = fmaf(v4.y, ex, acc.y);
        acc.z = fmaf(v4.z, ex, acc.z);
        acc.w = fmaf(v4.w, ex, acc.w);
        s0a = fmaf(ep.x, ex, s0a);
        s1a = fmaf(ep.y, ex, s1a);
    }

    float4 num = acc;
#pragma unroll
    for (int i = 0; i < 8; i++) {
        float sa = __shfl_sync(FULL, s0a, gb + i);
        float sb2 = __shfl_sync(FULL, s1a, gb + i);
        num.x = fmaf(sa, wreg[2 * i].x, num.x); num.x = fmaf(sb2, wreg[2 * i + 1].x, num.x);
        num.y = fmaf(sa, wreg[2 * i].y, num.y); num.y = fmaf(sb2, wreg[2 * i + 1].y, num.y);
        num.z = fmaf(sa, wreg[2 * i].z, num.z); num.z = fmaf(sb2, wreg[2 * i + 1].z, num.z);
        num.w = fmaf(sa, wreg[2 * i].w, num.w); num.w = fmaf(sb2, wreg[2 * i + 1].w, num.w);
    }

    float inv = 1.0f / (dsum + 1e-16f);
    float4 sk = *(const float4*)(d_qkvs + (size_t)n * 512 + 384 + lane * 4);
    float4 o;
    o.x = fmaxf(fmaf(num.x, inv, sk.x), 0.0f);
    o.y = fmaxf(fmaf(num.y, inv, sk.y), 0.0f);
    o.z = fmaxf(fmaf(num.z, inv, sk.z), 0.0f);
    o.w = fmaxf(fmaf(num.w, inv, sk.w), 0.0f);

    if (!doOut) {
        *(float4*)(d_h + (size_t)n * 128 + lane * 4) = o;
        return;
    }

    // ---- fused output head: logits + log_softmax (identical math to out_kernel)
    float lg[10];
#pragma unroll
    for (int cc = 0; cc < 10; cc++) {
        float pp = o.x * sW[(lane * 4 + 0) * 10 + cc] +
                   o.y * sW[(lane * 4 + 1) * 10 + cc] +
                   o.z * sW[(lane * 4 + 2) * 10 + cc] +
                   o.w * sW[(lane * 4 + 3) * 10 + cc];
        pp += __shfl_xor_sync(FULL, pp, 16);
        pp += __shfl_xor_sync(FULL, pp, 8);
        pp += __shfl_xor_sync(FULL, pp, 4);
        pp += __shfl_xor_sync(FULL, pp, 2);
        pp += __shfl_xor_sync(FULL, pp, 1);
        lg[cc] = pp + sb[cc];
    }
    float mx = lg[0];
#pragma unroll
    for (int cc = 1; cc < 10; cc++) mx = fmaxf(mx, lg[cc]);
    float ss = 0.0f;
#pragma unroll
    for (int cc = 0; cc < 10; cc++) ss += __expf(lg[cc] - mx);
    float lse = mx + logf(ss);
    if (lane == 0) {
#pragma unroll
        for (int cc = 0; cc < 10; cc++)
            out[(size_t)n * 10 + cc] = lg[cc] - lse;
    }
}

// ---------------------------------------------------------------------------
// Launch: CSR on a fork stream; pack0+pack1 hoisted; fused head in attn1.
// ---------------------------------------------------------------------------
extern "C" void kernel_launch(void* const* d_in, const int* in_sizes, int n_in,
                              void* d_out, int out_size) {
    const float* x     = (const float*)d_in[0];
    const int*   ei    = (const int*)d_in[1];
    const float* eattr = (const float*)d_in[2];
    const float* Wout = (const float*)d_in[21];
    const float* bout = (const float*)d_in[22];
    float* out = (float*)d_out;

    const int* src = ei;
    const int* dst = ei + EE;

    const int PACK_BLKS = (64 * 512 + 255) / 256;
    const int EDGE_BLKS = (EE + 255) / 256;
    const int NODE_BLKS = (NN + 255) / 256;
    const int ATTN_BLKS = (NN * 32 + 127) / 128;
    dim3 gemmGrid(4, (NN + 127) / 128);

    const float* W0[9], *W1[9];
    for (int i = 0; i < 9; i++) { W0[i] = (const float*)d_in[3 + i]; W1[i] = (const float*)d_in[12 + i]; }

    static cudaStream_t s2 = nullptr;
    static cudaEvent_t evFork = nullptr, evJoin = nullptr;
    if (s2 == nullptr) {
        cudaStreamCreateWithFlags(&s2, cudaStreamNonBlocking);
        cudaEventCreateWithFlags(&evFork, cudaEventDisableTiming);
        cudaEventCreateWithFlags(&evJoin, cudaEventDisableTiming);
    }

    // fork: CSR build on s2
    cudaEventRecord(evFork, 0);
    cudaStreamWaitEvent(s2, evFork, 0);

    zero_deg<<<NODE_BLKS, 256, 0, s2>>>();
    hist_kernel<<<EDGE_BLKS, 256, 0, s2>>>(dst);
    chunk_sums<<<NCHUNK, 256, 0, s2>>>();
    chunk_offsets<<<1, 256, 0, s2>>>();
    scan_chunks<<<NCHUNK, 256, 0, s2>>>();
    scatter_perm<<<EDGE_BLKS, 256, 0, s2>>>(dst, src);
    cudaEventRecord(evJoin, s2);

    // main stream: both packs, then layer pipeline
    pack_kernel<<<PACK_BLKS, 256>>>(W0[0], W0[2], W0[4], W0[7], W0[1], W0[3], W0[5], W0[8], 0);
    pack_kernel<<<PACK_BLKS, 256>>>(W1[0], W1[2], W1[4], W1[7], W1[1], W1[3], W1[5], W1[8], 1);
    sgemm_bf16x3<<<gemmGrid, 256>>>(x, 0, NN);

    cudaStreamWaitEvent(0, evJoin, 0);
    attn_node<<<ATTN_BLKS, 128>>>(eattr, W0[6], nullptr, nullptr, nullptr, 0);

    sgemm_bf16x3<<<gemmGrid, 256>>>(nullptr, 1, NN);
    attn_node<<<ATTN_BLKS, 128>>>(eattr, W1[6], Wout, bout, out, 1);
}

// round 13
// speedup vs baseline: 1.4444x; 1.4444x over previous
#include <cuda_runtime.h>
#include <cuda_bf16.h>
#include <cstdint>

// Problem constants (fixed by the dataset)
#define NN   50000
#define EE   600000
#define FD   128
#define EDIM 16
#define HH   4
#define DD   32
#define HIDD 128
#define CC   10

#define NCHUNK 196   // ceil(NN/256)

// ---------------------------------------------------------------------------
// Scratch (device globals; allocation-free per harness rules)
// ---------------------------------------------------------------------------
__device__ __align__(16) float d_qkvs[(size_t)NN * 512];   // q|k|v|skip packed per node
__device__ __align__(16) float d_h[(size_t)NN * 128];      // layer-0 output
// B in bf16 hi/lo, FRAGMENT-ordered, per layer
__device__ __align__(16) uint32_t d_WfH[2][8 * 16 * 32 * 8];
__device__ __align__(16) uint32_t d_WfL[2][8 * 16 * 32 * 8];
__device__ __align__(16) float d_bp[2][512];

// CSR-by-dst (built once per launch, shared by both layers)
__device__ int d_deg[NN];
__device__ int d_start[NN];
__device__ int d_cursor[NN];
__device__ int2 d_edge[EE];  // (edge id, src node) permuted by dst
__device__ int d_csums[256];
__device__ int d_coffs[256];

// ---------------------------------------------------------------------------
// Helpers
// ---------------------------------------------------------------------------
__device__ __forceinline__ int warp_incl_scan(int v, int lane) {
#pragma unroll
    for (int o = 1; o < 32; o <<= 1) {
        int n = __shfl_up_sync(0xffffffffu, v, o);
        if (lane >= o) v += n;
    }
    return v;
}

__device__ __forceinline__ void split_bf16x2(float f0, float f1,
                                             uint32_t& hi, uint32_t& lo) {
    __nv_bfloat162 hp = __float22bfloat162_rn(make_float2(f0, f1));
    hi = *reinterpret_cast<uint32_t*>(&hp);
    float r0 = f0 - __low2float(hp);
    float r1 = f1 - __high2float(hp);
    __nv_bfloat162 lp = __float22bfloat162_rn(make_float2(r0, r1));
    lo = *reinterpret_cast<uint32_t*>(&lp);
}

__device__ __forceinline__ uint32_t smem_u32(const void* p) {
    return (uint32_t)__cvta_generic_to_shared(p);
}

// ---------------------------------------------------------------------------
// CSR build
// ---------------------------------------------------------------------------
__global__ void zero_deg() {
    int i = blockIdx.x * blockDim.x + threadIdx.x;
    if (i < NN) d_deg[i] = 0;
}

__global__ void hist_kernel(const int* __restrict__ dst) {
    int e = blockIdx.x * blockDim.x + threadIdx.x;
    if (e < EE) atomicAdd(&d_deg[dst[e]], 1);
}

__global__ void chunk_sums() {
    int tid = threadIdx.x, b = blockIdx.x, i = b * 256 + tid;
    int v = (i < NN) ? d_deg[i] : 0;
#pragma unroll
    for (int o = 16; o > 0; o >>= 1) v += __shfl_xor_sync(0xffffffffu, v, o);
    __shared__ int ws[8];
    if ((tid & 31) == 0) ws[tid >> 5] = v;
    __syncthreads();
    if (tid == 0) {
        int s = 0;
#pragma unroll
        for (int k = 0; k < 8; k++) s += ws[k];
        d_csums[b] = s;
    }
}

__global__ void chunk_offsets() {   // single block, 256 threads
    int tid = threadIdx.x;
    int lane = tid & 31, w = tid >> 5;
    __shared__ int ws[8];
    int v = (tid < NCHUNK) ? d_csums[tid] : 0;
    int incl = warp_incl_scan(v, lane);
    if (lane == 31) ws[w] = incl;
    __syncthreads();
    if (w == 0) {
        int t = (lane < 8) ? ws[lane] : 0;
        t = warp_incl_scan(t, lane);
        if (lane < 8) ws[lane] = t;
    }
    __syncthreads();
    int excl = incl - v + (w > 0 ? ws[w - 1] : 0);
    d_coffs[tid] = excl;
}

__global__ void scan_chunks() {
    int tid = threadIdx.x, b = blockIdx.x, i = b * 256 + tid;
    int lane = tid & 31, w = tid >> 5;
    __shared__ int ws[8];
    int v = (i < NN) ? d_deg[i] : 0;
    int incl = warp_incl_scan(v, lane);
    if (lane == 31) ws[w] = incl;
    __syncthreads();
    if (w == 0) {
        int t = (lane < 8) ? ws[lane] : 0;
        t = warp_incl_scan(t, lane);
        if (lane < 8) ws[lane] = t;
    }
    __syncthreads();
    int excl = incl - v + (w > 0 ? ws[w - 1] : 0) + d_coffs[b];
    if (i < NN) { d_start[i] = excl; d_cursor[i] = excl; }
}

__global__ void scatter_perm(const int* __restrict__ dst, const int* __restrict__ src) {
    int e = blockIdx.x * blockDim.x + threadIdx.x;
    if (e < EE) {
        int pos = atomicAdd(&d_cursor[dst[e]], 1);
        d_edge[pos] = make_int2(e, src[e]);
    }
}

// ---------------------------------------------------------------------------
// Pack weights (per layer slot): bf16 hi/lo split, FRAGMENT order
// ---------------------------------------------------------------------------
__global__ void pack_kernel(const float* __restrict__ Wq, const float* __restrict__ Wk,
                            const float* __restrict__ Wv, const float* __restrict__ Ws,
                            const float* __restrict__ bq, const float* __restrict__ bk,
                            const float* __restrict__ bv, const float* __restrict__ bs,
                            int slot) {
    int idx = blockIdx.x * blockDim.x + threadIdx.x;
    if (idx < 64 * 512) {
        int kp = idx >> 9, col = idx & 511;
        int sel = col >> 7, jc = col & 127;
        const float* W = sel == 0 ? Wq : sel == 1 ? Wk : sel == 2 ? Wv : Ws;
        float f0 = W[(2 * kp) * 128 + jc];
        float f1 = W[(2 * kp + 1) * 128 + jc];
        uint32_t hi, lo;
        split_bf16x2(f0, f1, hi, lo);
        int ch = kp >> 3, kpl = kp & 7;
        int kh = kpl >> 2, tg = kpl & 3;
        int seg = col >> 5, g = col & 7, nt = (col >> 3) & 3;
        int off = ((ch * 16 + seg) * 32 + g * 4 + tg) * 8 + kh * 4 + nt;
        d_WfH[slot][off] = hi;
        d_WfL[slot][off] = lo;
    }
    if (idx < 512) {
        int sel = idx >> 7, jc = idx & 127;
        const float* b = sel == 0 ? bq : sel == 1 ? bk : sel == 2 ? bv : bs;
        d_bp[slot][idx] = b[jc];
    }
}

// ---------------------------------------------------------------------------
// bf16x3 tensor-core GEMM (R10 form, layer-indexed weights)
// ---------------------------------------------------------------------------
#define KC 16

__global__ void __launch_bounds__(256, 2) sgemm_bf16x3(const float* __restrict__ x,
                                                       int layer, int M) {
    const float* A = (layer == 0) ? x : (const float*)d_h;

    __shared__ __align__(16) uint32_t AsH[2][128][8];
    __shared__ __align__(16) uint32_t AsL[2][128][8];
    __shared__ __align__(16) uint32_t BfH[2][4][32][12];
    __shared__ __align__(16) uint32_t BfL[2][4][32][12];

    int tid = threadIdx.x;
    int bx = blockIdx.x;
    int by = blockIdx.y;
    int warp = tid >> 5, lane = tid & 31;
    int wm = warp >> 2, wn = warp & 3;
    int mbase = wm * 64, nbase = wn * 32;
    int rowBase = by * 128;
    int g = lane >> 2;
    int tg = lane & 3;

    int aR0 = tid >> 2,          aC0 = tid & 3;
    int aR1 = (tid + 256) >> 2,  aC1 = (tid + 256) & 3;
    int aI0a = (aC0 & 1) * 4 + (aC0 >> 1), aI0b = aI0a + 2;
    int aI1a = (aC1 & 1) * 4 + (aC1 >> 1), aI1b = aI1a + 2;

    float c[4][4][4];
#pragma unroll
    for (int i = 0; i < 4; i++)
#pragma unroll
        for (int j = 0; j < 4; j++)
#pragma unroll
            for (int r = 0; r < 4; r++) c[i][j][r] = 0.0f;

    float4 aReg0, aReg1;
    int grA0 = rowBase + aR0, grA1 = rowBase + aR1;
    bool a0OK = (grA0 < M), a1OK = (grA1 < M);

    int wnT = tid >> 6, laneT = (tid >> 1) & 31, halfT = tid & 1;
    uint32_t dBH0 = smem_u32(&BfH[0][0][0][0]) + ((wnT * 32 + laneT) * 12 + halfT * 4) * 4;
    uint32_t dBL0 = smem_u32(&BfL[0][0][0][0]) + ((wnT * 32 + laneT) * 12 + halfT * 4) * 4;
    const uint32_t* gBH = d_WfH[layer] + (size_t)bx * 4 * 256 + tid * 4;
    const uint32_t* gBL = d_WfL[layer] + (size_t)bx * 4 * 256 + tid * 4;
    const uint32_t stageBytes = 4 * 32 * 12 * 4;

    auto stageB = [&](int ch, int st) {
        uint32_t dH = dBH0 + st * stageBytes;
        uint32_t dL = dBL0 + st * stageBytes;
        const uint32_t* sH = gBH + ch * 4096;
        const uint32_t* sL = gBL + ch * 4096;
        asm volatile("cp.async.ca.shared.global [%0], [%1], 16;" :: "r"(dH), "l"(sH));
        asm volatile("cp.async.ca.shared.global [%0], [%1], 16;" :: "r"(dL), "l"(sL));
        asm volatile("cp.async.commit_group;");
    };

    auto loadA = [&](int ch) {
        int k0 = ch * KC;
        aReg0 = a0OK ? *(const float4*)(A + (size_t)grA0 * 128 + k0 + aC0 * 4)
                     : make_float4(0.f, 0.f, 0.f, 0.f);
        aReg1 = a1OK ? *(const float4*)(A + (size_t)grA1 * 128 + k0 + aC1 * 4)
                     : make_float4(0.f, 0.f, 0.f, 0.f);
    };

    auto storeA = [&](int st) {
        uint32_t h0, l0, h1, l1;
        split_bf16x2(aReg0.x, aReg0.y, h0, l0);
        split_bf16x2(aReg0.z, aReg0.w, h1, l1);
        AsH[st][aR0][aI0a] = h0;  AsH[st][aR0][aI0b] = h1;
        AsL[st][aR0][aI0a] = l0;  AsL[st][aR0][aI0b] = l1;
        split_bf16x2(aReg1.x, aReg1.y, h0, l0);
        split_bf16x2(aReg1.z, aReg1.w, h1, l1);
        AsH[st][aR1][aI1a] = h0;  AsH[st][aR1][aI1b] = h1;
        AsL[st][aR1][aI1a] = l0;  AsL[st][aR1][aI1b] = l1;
    };

    auto computeChunk = [&](int st) {
        const uint32_t* pH = &BfH[st][wn][lane][0];
        const uint32_t* pL = &BfL[st][wn][lane][0];
        uint4 bh0 = *(const uint4*)pH;
        uint4 bh1 = *(const uint4*)(pH + 4);
        uint4 bl0 = *(const uint4*)pL;
        uint4 bl1 = *(const uint4*)(pL + 4);
        uint32_t bh[4][2] = {{bh0.x, bh1.x}, {bh0.y, bh1.y}, {bh0.z, bh1.z}, {bh0.w, bh1.w}};
        uint32_t bl[4][2] = {{bl0.x, bl1.x}, {bl0.y, bl1.y}, {bl0.z, bl1.z}, {bl0.w, bl1.w}};
#pragma unroll
        for (int mt = 0; mt < 4; mt++) {
            int r = mbase + mt * 16 + g;
            uint2 ah0 = *(const uint2*)&AsH[st][r][2 * tg];
            uint2 ah1 = *(const uint2*)&AsH[st][r + 8][2 * tg];
            uint2 al0 = *(const uint2*)&AsL[st][r][2 * tg];
            uint2 al1 = *(const uint2*)&AsL[st][r + 8][2 * tg];
#pragma unroll
            for (int nt = 0; nt < 4; nt++) {
                float* cc = c[mt][nt];
                asm volatile(
                    "mma.sync.aligned.m16n8k16.row.col.f32.bf16.bf16.f32 "
                    "{%0,%1,%2,%3},{%4,%5,%6,%7},{%8,%9},{%0,%1,%2,%3};"
                    : "+f"(cc[0]), "+f"(cc[1]), "+f"(cc[2]), "+f"(cc[3])
                    : "r"(ah0.x), "r"(ah1.x), "r"(ah0.y), "r"(ah1.y),
                      "r"(bh[nt][0]), "r"(bh[nt][1]));
                asm volatile(
                    "mma.sync.aligned.m16n8k16.row.col.f32.bf16.bf16.f32 "
                    "{%0,%1,%2,%3},{%4,%5,%6,%7},{%8,%9},{%0,%1,%2,%3};"
                    : "+f"(cc[0]), "+f"(cc[1]), "+f"(cc[2]), "+f"(cc[3])
                    : "r"(ah0.x), "r"(ah1.x), "r"(ah0.y), "r"(ah1.y),
                      "r"(bl[nt][0]), "r"(bl[nt][1]));
                asm volatile(
                    "mma.sync.aligned.m16n8k16.row.col.f32.bf16.bf16.f32 "
                    "{%0,%1,%2,%3},{%4,%5,%6,%7},{%8,%9},{%0,%1,%2,%3};"
                    : "+f"(cc[0]), "+f"(cc[1]), "+f"(cc[2]), "+f"(cc[3])
                    : "r"(al0.x), "r"(al1.x), "r"(al0.y), "r"(al1.y),
                      "r"(bh[nt][0]), "r"(bh[nt][1]));
            }
        }
    };

    stageB(0, 0);
    loadA(0);
    storeA(0);
    asm volatile("cp.async.wait_group 0;" ::: "memory");
    __syncthreads();
#pragma unroll
    for (int ch = 0; ch < 8; ch++) {
        int cur = ch & 1;
        if (ch < 7) {
            loadA(ch + 1);
            stageB(ch + 1, cur ^ 1);
        }
        computeChunk(cur);
        if (ch < 7) {
            storeA(cur ^ 1);
            asm volatile("cp.async.wait_group 0;" ::: "memory");
            __syncthreads();
        }
    }

#pragma unroll
    for (int mt = 0; mt < 4; mt++) {
        int r0 = rowBase + mbase + mt * 16 + g;
        int r1 = r0 + 8;
#pragma unroll
        for (int nt = 0; nt < 4; nt++) {
            int col = bx * 128 + nbase + nt * 8 + 2 * tg;
            float2 b2 = *(const float2*)(d_bp[layer] + col);
            if (r0 < M) {
                float2 o = make_float2(c[mt][nt][0] + b2.x, c[mt][nt][1] + b2.y);
                *(float2*)(d_qkvs + (size_t)r0 * 512 + col) = o;
            }
            if (r1 < M) {
                float2 o = make_float2(c[mt][nt][2] + b2.x, c[mt][nt][3] + b2.y);
                *(float2*)(d_qkvs + (size_t)r1 * 512 + col) = o;
            }
        }
    }
}

// ===========================================================================
// Attention core (shared between the plain and fused-output kernels).
// Computes o = relu(attention + skip) for node n; returns it per-lane.
// ===========================================================================
__device__ __forceinline__ float4 attn_core(int n, int lane,
                                            const float* __restrict__ eattr,
                                            const float4* wreg) {
    const unsigned FULL = 0xffffffffu;
    int p = lane & 7;
    int gb = lane & 24;

    float4 q4 = *(const float4*)(d_qkvs + (size_t)n * 512 + lane * 4);

    float pk[16];
#pragma unroll
    for (int k = 0; k < 16; k++)
        pk[k] = q4.x * wreg[k].x + q4.y * wreg[k].y +
                q4.z * wreg[k].z + q4.w * wreg[k].w;
    float u[8];
#pragma unroll
    for (int i = 0; i < 8; i++) {
        float keep  = (lane & 4) ? pk[i + 8] : pk[i];
        float other = (lane & 4) ? pk[i] : pk[i + 8];
        u[i] = keep + __shfl_xor_sync(FULL, other, 4);
    }
    float w4[4];
#pragma unroll
    for (int i = 0; i < 4; i++) {
        float keep  = (lane & 2) ? u[i + 4] : u[i];
        float other = (lane & 2) ? u[i] : u[i + 4];
        w4[i] = keep + __shfl_xor_sync(FULL, other, 2);
    }
    float z0, z1;
    {
        float k0 = (lane & 1) ? w4[2] : w4[0];
        float o0 = (lane & 1) ? w4[0] : w4[2];
        z0 = k0 + __shfl_xor_sync(FULL, o0, 1);
        float k1 = (lane & 1) ? w4[3] : w4[1];
        float o1 = (lane & 1) ? w4[1] : w4[3];
        z1 = k1 + __shfl_xor_sync(FULL, o1, 1);
    }

    float4 acc = make_float4(0.f, 0.f, 0.f, 0.f);
    float s0a = 0.0f, s1a = 0.0f;
    float dsum = 0.0f;

    int start = d_start[n];
    int deg = d_deg[n];
    const float SC = 0.17677669529663687f;

    int j = 0;
    for (; j + 3 < deg; j += 4) {
        int2 ed0 = __ldg(&d_edge[start + j]);
        int2 ed1 = __ldg(&d_edge[start + j + 1]);
        int2 ed2 = __ldg(&d_edge[start + j + 2]);
        int2 ed3 = __ldg(&d_edge[start + j + 3]);

        float2 ep0 = *(const float2*)(eattr + (size_t)ed0.x * 16 + 2 * p);
        float2 ep1 = *(const float2*)(eattr + (size_t)ed1.x * 16 + 2 * p);
        float2 ep2 = *(const float2*)(eattr + (size_t)ed2.x * 16 + 2 * p);
        float2 ep3 = *(const float2*)(eattr + (size_t)ed3.x * 16 + 2 * p);

        const float* b0 = d_qkvs + (size_t)ed0.y * 512;
        const float* b1 = d_qkvs + (size_t)ed1.y * 512;
        const float* b2 = d_qkvs + (size_t)ed2.y * 512;
        const float* b3 = d_qkvs + (size_t)ed3.y * 512;
        float4 k40 = *(const float4*)(b0 + 128 + lane * 4);
        float4 k41 = *(const float4*)(b1 + 128 + lane * 4);
        float4 k42 = *(const float4*)(b2 + 128 + lane * 4);
        float4 k43 = *(const float4*)(b3 + 128 + lane * 4);
        float4 v40 = *(const float4*)(b0 + 256 + lane * 4);
        float4 v41 = *(const float4*)(b1 + 256 + lane * 4);
        float4 v42 = *(const float4*)(b2 + 256 + lane * 4);
        float4 v43 = *(const float4*)(b3 + 256 + lane * 4);

        float t0 = q4.x * k40.x + q4.y * k40.y + q4.z * k40.z + q4.w * k40.w +
                   ep0.x * z0 + ep0.y * z1;
        float t1 = q4.x * k41.x + q4.y * k41.y + q4.z * k41.z + q4.w * k41.w +
                   ep1.x * z0 + ep1.y * z1;
        float t2 = q4.x * k42.x + q4.y * k42.y + q4.z * k42.z + q4.w * k42.w +
                   ep2.x * z0 + ep2.y * z1;
        float t3 = q4.x * k43.x + q4.y * k43.y + q4.z * k43.z + q4.w * k43.w +
                   ep3.x * z0 + ep3.y * z1;
        t0 += __shfl_xor_sync(FULL, t0, 1);
        t1 += __shfl_xor_sync(FULL, t1, 1);
        t2 += __shfl_xor_sync(FULL, t2, 1);
        t3 += __shfl_xor_sync(FULL, t3, 1);
        t0 += __shfl_xor_sync(FULL, t0, 2);
        t1 += __shfl_xor_sync(FULL, t1, 2);
        t2 += __shfl_xor_sync(FULL, t2, 2);
        t3 += __shfl_xor_sync(FULL, t3, 2);
        t0 += __shfl_xor_sync(FULL, t0, 4);
        t1 += __shfl_xor_sync(FULL, t1, 4);
        t2 += __shfl_xor_sync(FULL, t2, 4);
        t3 += __shfl_xor_sync(FULL, t3, 4);

        float ex0 = __expf(t0 * SC);
        float ex1 = __expf(t1 * SC);
        float ex2 = __expf(t2 * SC);
        float ex3 = __expf(t3 * SC);
        dsum += (ex0 + ex1) + (ex2 + ex3);
        acc.x = fmaf(v40.x, ex0, acc.x);  acc.x = fmaf(v41.x, ex1, acc.x);
        acc.x = fmaf(v42.x, ex2, acc.x);  acc.x = fmaf(v43.x, ex3, acc.x);
        acc.y = fmaf(v40.y, ex0, acc.y);  acc.y = fmaf(v41.y, ex1, acc.y);
        acc.y = fmaf(v42.y, ex2, acc.y);  acc.y = fmaf(v43.y, ex3, acc.y);
        acc.z = fmaf(v40.z, ex0, acc.z);  acc.z = fmaf(v41.z, ex1, acc.z);
        acc.z = fmaf(v42.z, ex2, acc.z);  acc.z = fmaf(v43.z, ex3, acc.z);
        acc.w = fmaf(v40.w, ex0, acc.w);  acc.w = fmaf(v41.w, ex1, acc.w);
        acc.w = fmaf(v42.w, ex2, acc.w);  acc.w = fmaf(v43.w, ex3, acc.w);
        s0a = fmaf(ep0.x, ex0, s0a);      s0a = fmaf(ep1.x, ex1, s0a);
        s0a = fmaf(ep2.x, ex2, s0a);      s0a = fmaf(ep3.x, ex3, s0a);
        s1a = fmaf(ep0.y, ex0, s1a);      s1a = fmaf(ep1.y, ex1, s1a);
        s1a = fmaf(ep2.y, ex2, s1a);      s1a = fmaf(ep3.y, ex3, s1a);
    }

    for (; j < deg; j++) {
        int2 ed = __ldg(&d_edge[start + j]);
        float2 ep = *(const float2*)(eattr + (size_t)ed.x * 16 + 2 * p);
        const float* base = d_qkvs + (size_t)ed.y * 512;
        float4 k4 = *(const float4*)(base + 128 + lane * 4);
        float4 v4 = *(const float4*)(base + 256 + lane * 4);
        float t = q4.x * k4.x + q4.y * k4.y + q4.z * k4.z + q4.w * k4.w +
                  ep.x * z0 + ep.y * z1;
        t += __shfl_xor_sync(FULL, t, 1);
        t += __shfl_xor_sync(FULL, t, 2);
        t += __shfl_xor_sync(FULL, t, 4);
        float ex = __expf(t * SC);
        dsum += ex;
        acc.x = fmaf(v4.x, ex, acc.x);
        acc.y = fmaf(v4.y, ex, acc.y);
        acc.z = fmaf(v4.z, ex, acc.z);
        acc.w = fmaf(v4.w, ex, acc.w);
        s0a = fmaf(ep.x, ex, s0a);
        s1a = fmaf(ep.y, ex, s1a);
    }

    float4 num = acc;
#pragma unroll
    for (int i = 0; i < 8; i++) {
        float sa = __shfl_sync(FULL, s0a, gb + i);
        float sb2 = __shfl_sync(FULL, s1a, gb + i);
        num.x = fmaf(sa, wreg[2 * i].x, num.x); num.x = fmaf(sb2, wreg[2 * i + 1].x, num.x);
        num.y = fmaf(sa, wreg[2 * i].y, num.y); num.y = fmaf(sb2, wreg[2 * i + 1].y, num.y);
        num.z = fmaf(sa, wreg[2 * i].z, num.z); num.z = fmaf(sb2, wreg[2 * i + 1].z, num.z);
        num.w = fmaf(sa, wreg[2 * i].w, num.w); num.w = fmaf(sb2, wreg[2 * i + 1].w, num.w);
    }

    float inv = 1.0f / (dsum + 1e-16f);
    float4 sk = *(const float4*)(d_qkvs + (size_t)n * 512 + 384 + lane * 4);
    float4 o;
    o.x = fmaxf(fmaf(num.x, inv, sk.x), 0.0f);
    o.y = fmaxf(fmaf(num.y, inv, sk.y), 0.0f);
    o.z = fmaxf(fmaf(num.z, inv, sk.z), 0.0f);
    o.w = fmaxf(fmaf(num.w, inv, sk.w), 0.0f);
    return o;
}

// ---------------------------------------------------------------------------
// Layer-0 attention: plain (R10 behavior, writes d_h)
// ---------------------------------------------------------------------------
__global__ void __launch_bounds__(128) attn_node(const float* __restrict__ eattr,
                                                 const float* __restrict__ We) {
    int warp = (blockIdx.x * 128 + threadIdx.x) >> 5;
    int lane = threadIdx.x & 31;
    if (warp >= NN) return;

    float4 wreg[16];
#pragma unroll
    for (int k = 0; k < 16; k++)
        wreg[k] = __ldg((const float4*)(We + k * 128) + lane);

    float4 o = attn_core(warp, lane, eattr, wreg);
    *(float4*)(d_h + (size_t)warp * 128 + lane * 4) = o;
}

// ---------------------------------------------------------------------------
// Layer-1 attention with fused output head (separate kernel => own regs)
// ---------------------------------------------------------------------------
__global__ void __launch_bounds__(128) attn_node_out(const float* __restrict__ eattr,
                                                     const float* __restrict__ We,
                                                     const float* __restrict__ Wout,
                                                     const float* __restrict__ bout,
                                                     float* __restrict__ out) {
    const unsigned FULL = 0xffffffffu;
    __shared__ float sW[128 * 10];
    __shared__ float sb[10];
    for (int i = threadIdx.x; i < 128 * 10; i += 128) sW[i] = Wout[i];
    if (threadIdx.x < 10) sb[threadIdx.x] = bout[threadIdx.x];
    __syncthreads();

    int warp = (blockIdx.x * 128 + threadIdx.x) >> 5;
    int lane = threadIdx.x & 31;
    if (warp >= NN) return;

    float4 wreg[16];
#pragma unroll
    for (int k = 0; k < 16; k++)
        wreg[k] = __ldg((const float4*)(We + k * 128) + lane);

    float4 o = attn_core(warp, lane, eattr, wreg);

    float lg[10];
#pragma unroll
    for (int cc = 0; cc < 10; cc++) {
        float pp = o.x * sW[(lane * 4 + 0) * 10 + cc] +
                   o.y * sW[(lane * 4 + 1) * 10 + cc] +
                   o.z * sW[(lane * 4 + 2) * 10 + cc] +
                   o.w * sW[(lane * 4 + 3) * 10 + cc];
        pp += __shfl_xor_sync(FULL, pp, 16);
        pp += __shfl_xor_sync(FULL, pp, 8);
        pp += __shfl_xor_sync(FULL, pp, 4);
        pp += __shfl_xor_sync(FULL, pp, 2);
        pp += __shfl_xor_sync(FULL, pp, 1);
        lg[cc] = pp + sb[cc];
    }
    float mx = lg[0];
#pragma unroll
    for (int cc = 1; cc < 10; cc++) mx = fmaxf(mx, lg[cc]);
    float ss = 0.0f;
#pragma unroll
    for (int cc = 0; cc < 10; cc++) ss += __expf(lg[cc] - mx);
    float lse = mx + logf(ss);
    if (lane == 0) {
#pragma unroll
        for (int cc = 0; cc < 10; cc++)
            out[(size_t)warp * 10 + cc] = lg[cc] - lse;
    }
}

// ---------------------------------------------------------------------------
// Launch: CSR on a fork stream; both packs hoisted; fused head only in layer 1.
// ---------------------------------------------------------------------------
extern "C" void kernel_launch(void* const* d_in, const int* in_sizes, int n_in,
                              void* d_out, int out_size) {
    const float* x     = (const float*)d_in[0];
    const int*   ei    = (const int*)d_in[1];
    const float* eattr = (const float*)d_in[2];
    const float* Wout = (const float*)d_in[21];
    const float* bout = (const float*)d_in[22];
    float* out = (float*)d_out;

    const int* src = ei;
    const int* dst = ei + EE;

    const int PACK_BLKS = (64 * 512 + 255) / 256;
    const int EDGE_BLKS = (EE + 255) / 256;
    const int NODE_BLKS = (NN + 255) / 256;
    const int ATTN_BLKS = (NN * 32 + 127) / 128;
    dim3 gemmGrid(4, (NN + 127) / 128);

    const float* W0[9], *W1[9];
    for (int i = 0; i < 9; i++) { W0[i] = (const float*)d_in[3 + i]; W1[i] = (const float*)d_in[12 + i]; }

    static cudaStream_t s2 = nullptr;
    static cudaEvent_t evFork = nullptr, evJoin = nullptr;
    if (s2 == nullptr) {
        cudaStreamCreateWithFlags(&s2, cudaStreamNonBlocking);
        cudaEventCreateWithFlags(&evFork, cudaEventDisableTiming);
        cudaEventCreateWithFlags(&evJoin, cudaEventDisableTiming);
    }

    // fork: CSR build on s2
    cudaEventRecord(evFork, 0);
    cudaStreamWaitEvent(s2, evFork, 0);

    zero_deg<<<NODE_BLKS, 256, 0, s2>>>();
    hist_kernel<<<EDGE_BLKS, 256, 0, s2>>>(dst);
    chunk_sums<<<NCHUNK, 256, 0, s2>>>();
    chunk_offsets<<<1, 256, 0, s2>>>();
    scan_chunks<<<NCHUNK, 256, 0, s2>>>();
    scatter_perm<<<EDGE_BLKS, 256, 0, s2>>>(dst, src);
    cudaEventRecord(evJoin, s2);

    // main stream
    pack_kernel<<<PACK_BLKS, 256>>>(W0[0], W0[2], W0[4], W0[7], W0[1], W0[3], W0[5], W0[8], 0);
    pack_kernel<<<PACK_BLKS, 256>>>(W1[0], W1[2], W1[4], W1[7], W1[1], W1[3], W1[5], W1[8], 1);
    sgemm_bf16x3<<<gemmGrid, 256>>>(x, 0, NN);

    cudaStreamWaitEvent(0, evJoin, 0);
    attn_node<<<ATTN_BLKS, 128>>>(eattr, W0[6]);

    sgemm_bf16x3<<<gemmGrid, 256>>>(nullptr, 1, NN);
    attn_node_out<<<ATTN_BLKS, 128>>>(eattr, W1[6], Wout, bout, out);
}

// round 14
// speedup vs baseline: 1.8292x; 1.2664x over previous
#include <cuda_runtime.h>
#include <cuda_bf16.h>
#include <cstdint>

// Problem constants (fixed by the dataset)
#define NN   50000
#define EE   600000
#define FD   128
#define EDIM 16
#define HH   4
#define DD   32
#define HIDD 128
#define CC   10

#define NCHUNK 196   // ceil(NN/256)

// ---------------------------------------------------------------------------
// Scratch (device globals; allocation-free per harness rules)
// ---------------------------------------------------------------------------
__device__ __align__(16) float d_qkvs[(size_t)NN * 512];   // q|k|v|skip packed per node
__device__ __align__(16) float d_h[(size_t)NN * 128];      // layer-0 output
// B in bf16 hi/lo, FRAGMENT-ordered, per layer
__device__ __align__(16) uint32_t d_WfH[2][8 * 16 * 32 * 8];
__device__ __align__(16) uint32_t d_WfL[2][8 * 16 * 32 * 8];
__device__ __align__(16) float d_bp[2][512];

// CSR-by-dst (built once per launch, shared by both layers)
__device__ int d_deg[NN];
__device__ int d_start[NN];
__device__ int d_cursor[NN];
__device__ int2 d_edge[EE];  // (edge id, src node) permuted by dst
__device__ int d_csums[256];
__device__ int d_coffs[256];

// ---------------------------------------------------------------------------
// Helpers
// ---------------------------------------------------------------------------
__device__ __forceinline__ int warp_incl_scan(int v, int lane) {
#pragma unroll
    for (int o = 1; o < 32; o <<= 1) {
        int n = __shfl_up_sync(0xffffffffu, v, o);
        if (lane >= o) v += n;
    }
    return v;
}

__device__ __forceinline__ void split_bf16x2(float f0, float f1,
                                             uint32_t& hi, uint32_t& lo) {
    __nv_bfloat162 hp = __float22bfloat162_rn(make_float2(f0, f1));
    hi = *reinterpret_cast<uint32_t*>(&hp);
    float r0 = f0 - __low2float(hp);
    float r1 = f1 - __high2float(hp);
    __nv_bfloat162 lp = __float22bfloat162_rn(make_float2(r0, r1));
    lo = *reinterpret_cast<uint32_t*>(&lp);
}

__device__ __forceinline__ uint32_t smem_u32(const void* p) {
    return (uint32_t)__cvta_generic_to_shared(p);
}

// volatile non-caching v4 load: prevents CSE with earlier loads of the same
// address, so We does NOT stay register-resident across the edge loop.
__device__ __forceinline__ float4 ldg_v4_volatile(const float* p) {
    float4 v;
    asm volatile("ld.global.nc.v4.f32 {%0,%1,%2,%3}, [%4];"
                 : "=f"(v.x), "=f"(v.y), "=f"(v.z), "=f"(v.w) : "l"(p));
    return v;
}

// ---------------------------------------------------------------------------
// CSR build
// ---------------------------------------------------------------------------
__global__ void zero_deg() {
    int i = blockIdx.x * blockDim.x + threadIdx.x;
    if (i < NN) d_deg[i] = 0;
}

__global__ void hist_kernel(const int* __restrict__ dst) {
    int e = blockIdx.x * blockDim.x + threadIdx.x;
    if (e < EE) atomicAdd(&d_deg[dst[e]], 1);
}

__global__ void chunk_sums() {
    int tid = threadIdx.x, b = blockIdx.x, i = b * 256 + tid;
    int v = (i < NN) ? d_deg[i] : 0;
#pragma unroll
    for (int o = 16; o > 0; o >>= 1) v += __shfl_xor_sync(0xffffffffu, v, o);
    __shared__ int ws[8];
    if ((tid & 31) == 0) ws[tid >> 5] = v;
    __syncthreads();
    if (tid == 0) {
        int s = 0;
#pragma unroll
        for (int k = 0; k < 8; k++) s += ws[k];
        d_csums[b] = s;
    }
}

__global__ void chunk_offsets() {   // single block, 256 threads
    int tid = threadIdx.x;
    int lane = tid & 31, w = tid >> 5;
    __shared__ int ws[8];
    int v = (tid < NCHUNK) ? d_csums[tid] : 0;
    int incl = warp_incl_scan(v, lane);
    if (lane == 31) ws[w] = incl;
    __syncthreads();
    if (w == 0) {
        int t = (lane < 8) ? ws[lane] : 0;
        t = warp_incl_scan(t, lane);
        if (lane < 8) ws[lane] = t;
    }
    __syncthreads();
    int excl = incl - v + (w > 0 ? ws[w - 1] : 0);
    d_coffs[tid] = excl;
}

__global__ void scan_chunks() {
    int tid = threadIdx.x, b = blockIdx.x, i = b * 256 + tid;
    int lane = tid & 31, w = tid >> 5;
    __shared__ int ws[8];
    int v = (i < NN) ? d_deg[i] : 0;
    int incl = warp_incl_scan(v, lane);
    if (lane == 31) ws[w] = incl;
    __syncthreads();
    if (w == 0) {
        int t = (lane < 8) ? ws[lane] : 0;
        t = warp_incl_scan(t, lane);
        if (lane < 8) ws[lane] = t;
    }
    __syncthreads();
    int excl = incl - v + (w > 0 ? ws[w - 1] : 0) + d_coffs[b];
    if (i < NN) { d_start[i] = excl; d_cursor[i] = excl; }
}

__global__ void scatter_perm(const int* __restrict__ dst, const int* __restrict__ src) {
    int e = blockIdx.x * blockDim.x + threadIdx.x;
    if (e < EE) {
        int pos = atomicAdd(&d_cursor[dst[e]], 1);
        d_edge[pos] = make_int2(e, src[e]);
    }
}

// ---------------------------------------------------------------------------
// Pack weights (per layer slot): bf16 hi/lo split, FRAGMENT order
// ---------------------------------------------------------------------------
__global__ void pack_kernel(const float* __restrict__ Wq, const float* __restrict__ Wk,
                            const float* __restrict__ Wv, const float* __restrict__ Ws,
                            const float* __restrict__ bq, const float* __restrict__ bk,
                            const float* __restrict__ bv, const float* __restrict__ bs,
                            int slot) {
    int idx = blockIdx.x * blockDim.x + threadIdx.x;
    if (idx < 64 * 512) {
        int kp = idx >> 9, col = idx & 511;
        int sel = col >> 7, jc = col & 127;
        const float* W = sel == 0 ? Wq : sel == 1 ? Wk : sel == 2 ? Wv : Ws;
        float f0 = W[(2 * kp) * 128 + jc];
        float f1 = W[(2 * kp + 1) * 128 + jc];
        uint32_t hi, lo;
        split_bf16x2(f0, f1, hi, lo);
        int ch = kp >> 3, kpl = kp & 7;
        int kh = kpl >> 2, tg = kpl & 3;
        int seg = col >> 5, g = col & 7, nt = (col >> 3) & 3;
        int off = ((ch * 16 + seg) * 32 + g * 4 + tg) * 8 + kh * 4 + nt;
        d_WfH[slot][off] = hi;
        d_WfL[slot][off] = lo;
    }
    if (idx < 512) {
        int sel = idx >> 7, jc = idx & 127;
        const float* b = sel == 0 ? bq : sel == 1 ? bk : sel == 2 ? bv : bs;
        d_bp[slot][idx] = b[jc];
    }
}

// ---------------------------------------------------------------------------
// bf16x3 tensor-core GEMM (R10 form, layer-indexed weights)
// ---------------------------------------------------------------------------
#define KC 16

__global__ void __launch_bounds__(256, 2) sgemm_bf16x3(const float* __restrict__ x,
                                                       int layer, int M) {
    const float* A = (layer == 0) ? x : (const float*)d_h;

    __shared__ __align__(16) uint32_t AsH[2][128][8];
    __shared__ __align__(16) uint32_t AsL[2][128][8];
    __shared__ __align__(16) uint32_t BfH[2][4][32][12];
    __shared__ __align__(16) uint32_t BfL[2][4][32][12];

    int tid = threadIdx.x;
    int bx = blockIdx.x;
    int by = blockIdx.y;
    int warp = tid >> 5, lane = tid & 31;
    int wm = warp >> 2, wn = warp & 3;
    int mbase = wm * 64, nbase = wn * 32;
    int rowBase = by * 128;
    int g = lane >> 2;
    int tg = lane & 3;

    int aR0 = tid >> 2,          aC0 = tid & 3;
    int aR1 = (tid + 256) >> 2,  aC1 = (tid + 256) & 3;
    int aI0a = (aC0 & 1) * 4 + (aC0 >> 1), aI0b = aI0a + 2;
    int aI1a = (aC1 & 1) * 4 + (aC1 >> 1), aI1b = aI1a + 2;

    float c[4][4][4];
#pragma unroll
    for (int i = 0; i < 4; i++)
#pragma unroll
        for (int j = 0; j < 4; j++)
#pragma unroll
            for (int r = 0; r < 4; r++) c[i][j][r] = 0.0f;

    float4 aReg0, aReg1;
    int grA0 = rowBase + aR0, grA1 = rowBase + aR1;
    bool a0OK = (grA0 < M), a1OK = (grA1 < M);

    int wnT = tid >> 6, laneT = (tid >> 1) & 31, halfT = tid & 1;
    uint32_t dBH0 = smem_u32(&BfH[0][0][0][0]) + ((wnT * 32 + laneT) * 12 + halfT * 4) * 4;
    uint32_t dBL0 = smem_u32(&BfL[0][0][0][0]) + ((wnT * 32 + laneT) * 12 + halfT * 4) * 4;
    const uint32_t* gBH = d_WfH[layer] + (size_t)bx * 4 * 256 + tid * 4;
    const uint32_t* gBL = d_WfL[layer] + (size_t)bx * 4 * 256 + tid * 4;
    const uint32_t stageBytes = 4 * 32 * 12 * 4;

    auto stageB = [&](int ch, int st) {
        uint32_t dH = dBH0 + st * stageBytes;
        uint32_t dL = dBL0 + st * stageBytes;
        const uint32_t* sH = gBH + ch * 4096;
        const uint32_t* sL = gBL + ch * 4096;
        asm volatile("cp.async.ca.shared.global [%0], [%1], 16;" :: "r"(dH), "l"(sH));
        asm volatile("cp.async.ca.shared.global [%0], [%1], 16;" :: "r"(dL), "l"(sL));
        asm volatile("cp.async.commit_group;");
    };

    auto loadA = [&](int ch) {
        int k0 = ch * KC;
        aReg0 = a0OK ? *(const float4*)(A + (size_t)grA0 * 128 + k0 + aC0 * 4)
                     : make_float4(0.f, 0.f, 0.f, 0.f);
        aReg1 = a1OK ? *(const float4*)(A + (size_t)grA1 * 128 + k0 + aC1 * 4)
                     : make_float4(0.f, 0.f, 0.f, 0.f);
    };

    auto storeA = [&](int st) {
        uint32_t h0, l0, h1, l1;
        split_bf16x2(aReg0.x, aReg0.y, h0, l0);
        split_bf16x2(aReg0.z, aReg0.w, h1, l1);
        AsH[st][aR0][aI0a] = h0;  AsH[st][aR0][aI0b] = h1;
        AsL[st][aR0][aI0a] = l0;  AsL[st][aR0][aI0b] = l1;
        split_bf16x2(aReg1.x, aReg1.y, h0, l0);
        split_bf16x2(aReg1.z, aReg1.w, h1, l1);
        AsH[st][aR1][aI1a] = h0;  AsH[st][aR1][aI1b] = h1;
        AsL[st][aR1][aI1a] = l0;  AsL[st][aR1][aI1b] = l1;
    };

    auto computeChunk = [&](int st) {
        const uint32_t* pH = &BfH[st][wn][lane][0];
        const uint32_t* pL = &BfL[st][wn][lane][0];
        uint4 bh0 = *(const uint4*)pH;
        uint4 bh1 = *(const uint4*)(pH + 4);
        uint4 bl0 = *(const uint4*)pL;
        uint4 bl1 = *(const uint4*)(pL + 4);
        uint32_t bh[4][2] = {{bh0.x, bh1.x}, {bh0.y, bh1.y}, {bh0.z, bh1.z}, {bh0.w, bh1.w}};
        uint32_t bl[4][2] = {{bl0.x, bl1.x}, {bl0.y, bl1.y}, {bl0.z, bl1.z}, {bl0.w, bl1.w}};
#pragma unroll
        for (int mt = 0; mt < 4; mt++) {
            int r = mbase + mt * 16 + g;
            uint2 ah0 = *(const uint2*)&AsH[st][r][2 * tg];
            uint2 ah1 = *(const uint2*)&AsH[st][r + 8][2 * tg];
            uint2 al0 = *(const uint2*)&AsL[st][r][2 * tg];
            uint2 al1 = *(const uint2*)&AsL[st][r + 8][2 * tg];
#pragma unroll
            for (int nt = 0; nt < 4; nt++) {
                float* cc = c[mt][nt];
                asm volatile(
                    "mma.sync.aligned.m16n8k16.row.col.f32.bf16.bf16.f32 "
                    "{%0,%1,%2,%3},{%4,%5,%6,%7},{%8,%9},{%0,%1,%2,%3};"
                    : "+f"(cc[0]), "+f"(cc[1]), "+f"(cc[2]), "+f"(cc[3])
                    : "r"(ah0.x), "r"(ah1.x), "r"(ah0.y), "r"(ah1.y),
                      "r"(bh[nt][0]), "r"(bh[nt][1]));
                asm volatile(
                    "mma.sync.aligned.m16n8k16.row.col.f32.bf16.bf16.f32 "
                    "{%0,%1,%2,%3},{%4,%5,%6,%7},{%8,%9},{%0,%1,%2,%3};"
                    : "+f"(cc[0]), "+f"(cc[1]), "+f"(cc[2]), "+f"(cc[3])
                    : "r"(ah0.x), "r"(ah1.x), "r"(ah0.y), "r"(ah1.y),
                      "r"(bl[nt][0]), "r"(bl[nt][1]));
                asm volatile(
                    "mma.sync.aligned.m16n8k16.row.col.f32.bf16.bf16.f32 "
                    "{%0,%1,%2,%3},{%4,%5,%6,%7},{%8,%9},{%0,%1,%2,%3};"
                    : "+f"(cc[0]), "+f"(cc[1]), "+f"(cc[2]), "+f"(cc[3])
                    : "r"(al0.x), "r"(al1.x), "r"(al0.y), "r"(al1.y),
                      "r"(bh[nt][0]), "r"(bh[nt][1]));
            }
        }
    };

    stageB(0, 0);
    loadA(0);
    storeA(0);
    asm volatile("cp.async.wait_group 0;" ::: "memory");
    __syncthreads();
#pragma unroll
    for (int ch = 0; ch < 8; ch++) {
        int cur = ch & 1;
        if (ch < 7) {
            loadA(ch + 1);
            stageB(ch + 1, cur ^ 1);
        }
        computeChunk(cur);
        if (ch < 7) {
            storeA(cur ^ 1);
            asm volatile("cp.async.wait_group 0;" ::: "memory");
            __syncthreads();
        }
    }

#pragma unroll
    for (int mt = 0; mt < 4; mt++) {
        int r0 = rowBase + mbase + mt * 16 + g;
        int r1 = r0 + 8;
#pragma unroll
        for (int nt = 0; nt < 4; nt++) {
            int col = bx * 128 + nbase + nt * 8 + 2 * tg;
            float2 b2 = *(const float2*)(d_bp[layer] + col);
            if (r0 < M) {
                float2 o = make_float2(c[mt][nt][0] + b2.x, c[mt][nt][1] + b2.y);
                *(float2*)(d_qkvs + (size_t)r0 * 512 + col) = o;
            }
            if (r1 < M) {
                float2 o = make_float2(c[mt][nt][2] + b2.x, c[mt][nt][3] + b2.y);
                *(float2*)(d_qkvs + (size_t)r1 * 512 + col) = o;
            }
        }
    }
}

// ===========================================================================
// Attention core. We is NOT kept register-resident across the edge loop:
// phase-1 loads die after producing pk[]; finalize reloads via volatile LDG.
// ===========================================================================
__device__ __forceinline__ float4 attn_core(int n, int lane,
                                            const float* __restrict__ eattr,
                                            const float* __restrict__ We) {
    const unsigned FULL = 0xffffffffu;
    int p = lane & 7;
    int gb = lane & 24;

    float4 q4 = *(const float4*)(d_qkvs + (size_t)n * 512 + lane * 4);

    // phase 1: pk[k] = q . We[k][lane-cols]; each We row dies immediately
    float pk[16];
#pragma unroll
    for (int k = 0; k < 16; k++) {
        float4 w = __ldg((const float4*)(We + k * 128) + lane);
        pk[k] = q4.x * w.x + q4.y * w.y + q4.z * w.z + q4.w * w.w;
    }
    float u[8];
#pragma unroll
    for (int i = 0; i < 8; i++) {
        float keep  = (lane & 4) ? pk[i + 8] : pk[i];
        float other = (lane & 4) ? pk[i] : pk[i + 8];
        u[i] = keep + __shfl_xor_sync(FULL, other, 4);
    }
    float w4[4];
#pragma unroll
    for (int i = 0; i < 4; i++) {
        float keep  = (lane & 2) ? u[i + 4] : u[i];
        float other = (lane & 2) ? u[i] : u[i + 4];
        w4[i] = keep + __shfl_xor_sync(FULL, other, 2);
    }
    float z0, z1;
    {
        float k0 = (lane & 1) ? w4[2] : w4[0];
        float o0 = (lane & 1) ? w4[0] : w4[2];
        z0 = k0 + __shfl_xor_sync(FULL, o0, 1);
        float k1 = (lane & 1) ? w4[3] : w4[1];
        float o1 = (lane & 1) ? w4[1] : w4[3];
        z1 = k1 + __shfl_xor_sync(FULL, o1, 1);
    }

    float4 acc = make_float4(0.f, 0.f, 0.f, 0.f);
    float s0a = 0.0f, s1a = 0.0f;
    float dsum = 0.0f;

    int start = d_start[n];
    int deg = d_deg[n];
    const float SC = 0.17677669529663687f;

    int j = 0;
    for (; j + 3 < deg; j += 4) {
        int2 ed0 = __ldg(&d_edge[start + j]);
        int2 ed1 = __ldg(&d_edge[start + j + 1]);
        int2 ed2 = __ldg(&d_edge[start + j + 2]);
        int2 ed3 = __ldg(&d_edge[start + j + 3]);

        float2 ep0 = *(const float2*)(eattr + (size_t)ed0.x * 16 + 2 * p);
        float2 ep1 = *(const float2*)(eattr + (size_t)ed1.x * 16 + 2 * p);
        float2 ep2 = *(const float2*)(eattr + (size_t)ed2.x * 16 + 2 * p);
        float2 ep3 = *(const float2*)(eattr + (size_t)ed3.x * 16 + 2 * p);

        const float* b0 = d_qkvs + (size_t)ed0.y * 512;
        const float* b1 = d_qkvs + (size_t)ed1.y * 512;
        const float* b2 = d_qkvs + (size_t)ed2.y * 512;
        const float* b3 = d_qkvs + (size_t)ed3.y * 512;
        float4 k40 = *(const float4*)(b0 + 128 + lane * 4);
        float4 k41 = *(const float4*)(b1 + 128 + lane * 4);
        float4 k42 = *(const float4*)(b2 + 128 + lane * 4);
        float4 k43 = *(const float4*)(b3 + 128 + lane * 4);
        float4 v40 = *(const float4*)(b0 + 256 + lane * 4);
        float4 v41 = *(const float4*)(b1 + 256 + lane * 4);
        float4 v42 = *(const float4*)(b2 + 256 + lane * 4);
        float4 v43 = *(const float4*)(b3 + 256 + lane * 4);

        float t0 = q4.x * k40.x + q4.y * k40.y + q4.z * k40.z + q4.w * k40.w +
                   ep0.x * z0 + ep0.y * z1;
        float t1 = q4.x * k41.x + q4.y * k41.y + q4.z * k41.z + q4.w * k41.w +
                   ep1.x * z0 + ep1.y * z1;
        float t2 = q4.x * k42.x + q4.y * k42.y + q4.z * k42.z + q4.w * k42.w +
                   ep2.x * z0 + ep2.y * z1;
        float t3 = q4.x * k43.x + q4.y * k43.y + q4.z * k43.z + q4.w * k43.w +
                   ep3.x * z0 + ep3.y * z1;
        t0 += __shfl_xor_sync(FULL, t0, 1);
        t1 += __shfl_xor_sync(FULL, t1, 1);
        t2 += __shfl_xor_sync(FULL, t2, 1);
        t3 += __shfl_xor_sync(FULL, t3, 1);
        t0 += __shfl_xor_sync(FULL, t0, 2);
        t1 += __shfl_xor_sync(FULL, t1, 2);
        t2 += __shfl_xor_sync(FULL, t2, 2);
        t3 += __shfl_xor_sync(FULL, t3, 2);
        t0 += __shfl_xor_sync(FULL, t0, 4);
        t1 += __shfl_xor_sync(FULL, t1, 4);
        t2 += __shfl_xor_sync(FULL, t2, 4);
        t3 += __shfl_xor_sync(FULL, t3, 4);

        float ex0 = __expf(t0 * SC);
        float ex1 = __expf(t1 * SC);
        float ex2 = __expf(t2 * SC);
        float ex3 = __expf(t3 * SC);
        dsum += (ex0 + ex1) + (ex2 + ex3);
        acc.x = fmaf(v40.x, ex0, acc.x);  acc.x = fmaf(v41.x, ex1, acc.x);
        acc.x = fmaf(v42.x, ex2, acc.x);  acc.x = fmaf(v43.x, ex3, acc.x);
        acc.y = fmaf(v40.y, ex0, acc.y);  acc.y = fmaf(v41.y, ex1, acc.y);
        acc.y = fmaf(v42.y, ex2, acc.y);  acc.y = fmaf(v43.y, ex3, acc.y);
        acc.z = fmaf(v40.z, ex0, acc.z);  acc.z = fmaf(v41.z, ex1, acc.z);
        acc.z = fmaf(v42.z, ex2, acc.z);  acc.z = fmaf(v43.z, ex3, acc.z);
        acc.w = fmaf(v40.w, ex0, acc.w);  acc.w = fmaf(v41.w, ex1, acc.w);
        acc.w = fmaf(v42.w, ex2, acc.w);  acc.w = fmaf(v43.w, ex3, acc.w);
        s0a = fmaf(ep0.x, ex0, s0a);      s0a = fmaf(ep1.x, ex1, s0a);
        s0a = fmaf(ep2.x, ex2, s0a);      s0a = fmaf(ep3.x, ex3, s0a);
        s1a = fmaf(ep0.y, ex0, s1a);      s1a = fmaf(ep1.y, ex1, s1a);
        s1a = fmaf(ep2.y, ex2, s1a);      s1a = fmaf(ep3.y, ex3, s1a);
    }

    for (; j < deg; j++) {
        int2 ed = __ldg(&d_edge[start + j]);
        float2 ep = *(const float2*)(eattr + (size_t)ed.x * 16 + 2 * p);
        const float* base = d_qkvs + (size_t)ed.y * 512;
        float4 k4 = *(const float4*)(base + 128 + lane * 4);
        float4 v4 = *(const float4*)(base + 256 + lane * 4);
        float t = q4.x * k4.x + q4.y * k4.y + q4.z * k4.z + q4.w * k4.w +
                  ep.x * z0 + ep.y * z1;
        t += __shfl_xor_sync(FULL, t, 1);
        t += __shfl_xor_sync(FULL, t, 2);
        t += __shfl_xor_sync(FULL, t, 4);
        float ex = __expf(t * SC);
        dsum += ex;
        acc.x = fmaf(v4.x, ex, acc.x);
        acc.y = fmaf(v4.y, ex, acc.y);
        acc.z = fmaf(v4.z, ex, acc.z);
        acc.w = fmaf(v4.w, ex, acc.w);
        s0a = fmaf(ep.x, ex, s0a);
        s1a = fmaf(ep.y, ex, s1a);
    }

    // finalize: reload We (volatile -> no CSE with phase 1; L1/L2 hits)
    float4 num = acc;
#pragma unroll
    for (int i = 0; i < 8; i++) {
        float sa = __shfl_sync(FULL, s0a, gb + i);
        float sb2 = __shfl_sync(FULL, s1a, gb + i);
        float4 w0 = ldg_v4_volatile(We + (2 * i) * 128 + lane * 4);
        float4 w1 = ldg_v4_volatile(We + (2 * i + 1) * 128 + lane * 4);
        num.x = fmaf(sa, w0.x, num.x); num.x = fmaf(sb2, w1.x, num.x);
        num.y = fmaf(sa, w0.y, num.y); num.y = fmaf(sb2, w1.y, num.y);
        num.z = fmaf(sa, w0.z, num.z); num.z = fmaf(sb2, w1.z, num.z);
        num.w = fmaf(sa, w0.w, num.w); num.w = fmaf(sb2, w1.w, num.w);
    }

    float inv = 1.0f / (dsum + 1e-16f);
    float4 sk = *(const float4*)(d_qkvs + (size_t)n * 512 + 384 + lane * 4);
    float4 o;
    o.x = fmaxf(fmaf(num.x, inv, sk.x), 0.0f);
    o.y = fmaxf(fmaf(num.y, inv, sk.y), 0.0f);
    o.z = fmaxf(fmaf(num.z, inv, sk.z), 0.0f);
    o.w = fmaxf(fmaf(num.w, inv, sk.w), 0.0f);
    return o;
}

// ---------------------------------------------------------------------------
// Layer-0 attention: plain (writes d_h)
// ---------------------------------------------------------------------------
__global__ void __launch_bounds__(128) attn_node(const float* __restrict__ eattr,
                                                 const float* __restrict__ We) {
    int warp = (blockIdx.x * 128 + threadIdx.x) >> 5;
    int lane = threadIdx.x & 31;
    if (warp >= NN) return;

    float4 o = attn_core(warp, lane, eattr, We);
    *(float4*)(d_h + (size_t)warp * 128 + lane * 4) = o;
}

// ---------------------------------------------------------------------------
// Layer-1 attention with fused output head (separate kernel => own regs)
// ---------------------------------------------------------------------------
__global__ void __launch_bounds__(128) attn_node_out(const float* __restrict__ eattr,
                                                     const float* __restrict__ We,
                                                     const float* __restrict__ Wout,
                                                     const float* __restrict__ bout,
                                                     float* __restrict__ out) {
    const unsigned FULL = 0xffffffffu;
    __shared__ float sW[128 * 10];
    __shared__ float sb[10];
    for (int i = threadIdx.x; i < 128 * 10; i += 128) sW[i] = Wout[i];
    if (threadIdx.x < 10) sb[threadIdx.x] = bout[threadIdx.x];
    __syncthreads();

    int warp = (blockIdx.x * 128 + threadIdx.x) >> 5;
    int lane = threadIdx.x & 31;
    if (warp >= NN) return;

    float4 o = attn_core(warp, lane, eattr, We);

    float lg[10];
#pragma unroll
    for (int cc = 0; cc < 10; cc++) {
        float pp = o.x * sW[(lane * 4 + 0) * 10 + cc] +
                   o.y * sW[(lane * 4 + 1) * 10 + cc] +
                   o.z * sW[(lane * 4 + 2) * 10 + cc] +
                   o.w * sW[(lane * 4 + 3) * 10 + cc];
        pp += __shfl_xor_sync(FULL, pp, 16);
        pp += __shfl_xor_sync(FULL, pp, 8);
        pp += __shfl_xor_sync(FULL, pp, 4);
        pp += __shfl_xor_sync(FULL, pp, 2);
        pp += __shfl_xor_sync(FULL, pp, 1);
        lg[cc] = pp + sb[cc];
    }
    float mx = lg[0];
#pragma unroll
    for (int cc = 1; cc < 10; cc++) mx = fmaxf(mx, lg[cc]);
    float ss = 0.0f;
#pragma unroll
    for (int cc = 0; cc < 10; cc++) ss += __expf(lg[cc] - mx);
    float lse = mx + logf(ss);
    if (lane == 0) {
#pragma unroll
        for (int cc = 0; cc < 10; cc++)
            out[(size_t)warp * 10 + cc] = lg[cc] - lse;
    }
}

// ---------------------------------------------------------------------------
// Launch: CSR on a fork stream; both packs hoisted; fused head only in layer 1.
// ---------------------------------------------------------------------------
extern "C" void kernel_launch(void* const* d_in, const int* in_sizes, int n_in,
                              void* d_out, int out_size) {
    const float* x     = (const float*)d_in[0];
    const int*   ei    = (const int*)d_in[1];
    const float* eattr = (const float*)d_in[2];
    const float* Wout = (const float*)d_in[21];
    const float* bout = (const float*)d_in[22];
    float* out = (float*)d_out;

    const int* src = ei;
    const int* dst = ei + EE;

    const int PACK_BLKS = (64 * 512 + 255) / 256;
    const int EDGE_BLKS = (EE + 255) / 256;
    const int NODE_BLKS = (NN + 255) / 256;
    const int ATTN_BLKS = (NN * 32 + 127) / 128;
    dim3 gemmGrid(4, (NN + 127) / 128);

    const float* W0[9], *W1[9];
    for (int i = 0; i < 9; i++) { W0[i] = (const float*)d_in[3 + i]; W1[i] = (const float*)d_in[12 + i]; }

    static cudaStream_t s2 = nullptr;
    static cudaEvent_t evFork = nullptr, evJoin = nullptr;
    if (s2 == nullptr) {
        cudaStreamCreateWithFlags(&s2, cudaStreamNonBlocking);
        cudaEventCreateWithFlags(&evFork, cudaEventDisableTiming);
        cudaEventCreateWithFlags(&evJoin, cudaEventDisableTiming);
    }

    // fork: CSR build on s2
    cudaEventRecord(evFork, 0);
    cudaStreamWaitEvent(s2, evFork, 0);

    zero_deg<<<NODE_BLKS, 256, 0, s2>>>();
    hist_kernel<<<EDGE_BLKS, 256, 0, s2>>>(dst);
    chunk_sums<<<NCHUNK, 256, 0, s2>>>();
    chunk_offsets<<<1, 256, 0, s2>>>();
    scan_chunks<<<NCHUNK, 256, 0, s2>>>();
    scatter_perm<<<EDGE_BLKS, 256, 0, s2>>>(dst, src);
    cudaEventRecord(evJoin, s2);

    // main stream
    pack_kernel<<<PACK_BLKS, 256>>>(W0[0], W0[2], W0[4], W0[7], W0[1], W0[3], W0[5], W0[8], 0);
    pack_kernel<<<PACK_BLKS, 256>>>(W1[0], W1[2], W1[4], W1[7], W1[1], W1[3], W1[5], W1[8], 1);
    sgemm_bf16x3<<<gemmGrid, 256>>>(x, 0, NN);

    cudaStreamWaitEvent(0, evJoin, 0);
    attn_node<<<ATTN_BLKS, 128>>>(eattr, W0[6]);

    sgemm_bf16x3<<<gemmGrid, 256>>>(nullptr, 1, NN);
    attn_node_out<<<ATTN_BLKS, 128>>>(eattr, W1[6], Wout, bout, out);
}